// round 11
// baseline (speedup 1.0000x reference)
#include <cuda_runtime.h>
#include <math.h>

#define B 8
#define N 1024
#define C 256
#define K 256
#define C2 512
#define SCALE 0.17677669529663687f   // (C/H)^-0.5 = 1/sqrt(32)

// Output layout: [new_X (8*256*256) | new_adj (8*256*256) | new_mask (8*256)]
#define OUT_ADJ_OFF  (B*K*C)
#define OUT_MASK_OFF (2*B*K*C)

#define NCHUNK 64      // partial-sum chunks per batch (16 rows each)

// ---- scratch ----
__device__ float d_part[B*NCHUNK*C];
__device__ float d_u[B*C];
__device__ float d_scores[B*N];
__device__ int   d_idxg[B*K];
__device__ float d_gate[B*K];
__device__ float d_nm[B*K];

// ---------------------------------------------------------------------------
// K1: partial column sums of X (verbatim R2 — proven rounding).
// ---------------------------------------------------------------------------
__global__ void k_partial(const float* __restrict__ X) {
    int b = blockIdx.y, ch = blockIdx.x, c = threadIdx.x;
    const float* xp = X + ((size_t)b * N + (size_t)ch * 16) * C + c;
    float s = 0.f;
    #pragma unroll
    for (int r = 0; r < 16; r++) s += xp[(size_t)r * C];
    d_part[(b * NCHUNK + ch) * C + c] = s;
}

// ---------------------------------------------------------------------------
// K2: Xsum finish + two matvecs (verbatim R2 — proven rounding).
// ---------------------------------------------------------------------------
__global__ void k_uvec(const float* __restrict__ Wqkv) {
    int b = blockIdx.x, t = threadIdx.x;
    __shared__ float xs[C];
    __shared__ float ks[C];
    float s = 0.f;
    #pragma unroll
    for (int ch = 0; ch < NCHUNK; ch++) s += d_part[(b * NCHUNK + ch) * C + t];
    xs[t] = s;
    __syncthreads();
    float ka = 0.f;
    for (int c = 0; c < C; c++) ka += xs[c] * Wqkv[(size_t)c * C2 + C + t];
    ks[t] = ka;
    __syncthreads();
    const float* wrow = Wqkv + (size_t)t * C2;
    float ua = 0.f;
    for (int j = 0; j < C; j++) ua += wrow[j] * ks[j];
    d_u[b * C + t] = ua;
}

// ---------------------------------------------------------------------------
// K3: scores (verbatim R2 — proven rounding).
// ---------------------------------------------------------------------------
__global__ void k_scores(const float* __restrict__ X,
                         const float* __restrict__ mask) {
    int b = blockIdx.y, t = threadIdx.x;
    __shared__ float us[C];
    us[t] = d_u[b * C + t];
    __syncthreads();
    int warp = t >> 5, lane = t & 31;
    int n = blockIdx.x * 8 + warp;
    const float4* xr = (const float4*)(X + ((size_t)b * N + n) * C);
    const float4* ur = (const float4*)us;
    float acc = 0.f;
    #pragma unroll
    for (int it = 0; it < 2; it++) {
        float4 xv = xr[lane + it * 32];
        float4 uv = ur[lane + it * 32];
        acc += xv.x * uv.x + xv.y * uv.y + xv.z * uv.z + xv.w * uv.w;
    }
    #pragma unroll
    for (int o = 16; o; o >>= 1) acc += __shfl_xor_sync(0xffffffffu, acc, o);
    if (lane == 0) {
        float m = mask[b * N + n];
        d_scores[b * N + n] = (m > 0.f) ? SCALE * acc : -1e9f;
    }
}

// ---------------------------------------------------------------------------
// K4: rank selection, 4 threads per element. grid (8, 8), 512 threads.
// Combined key w[i] = (orderedFloat(score_i) << 10) | (N-1-i): all distinct;
// w_m > w_n  <=>  m outranks n. rank(n) = #{m : w_m > w_n} — computed as 4
// exact integer partial counts (one 256-key quarter per thread), summed in
// fixed order. Selection bit-identical to jax.lax.top_k and all passing
// rounds. 16 warps/block hide the LDS latency that capped R10.
// ---------------------------------------------------------------------------
__global__ void __launch_bounds__(512, 2)
k_rank(const float* __restrict__ mask, float* __restrict__ out) {
    int b = blockIdx.y, t = threadIdx.x;
    int e = t & 127;            // local element 0..127
    int q = t >> 7;             // m-range quarter 0..3
    __shared__ __align__(16) unsigned long long w[N];
    __shared__ int  rnk[512];
    __shared__ float red[16];
    __shared__ int s_ki;

    // build all 1024 keys for this batch (2 per thread, coalesced)
    for (int i = t; i < N; i += 512) {
        float f = d_scores[b * N + i];
        unsigned u = __float_as_uint(f);
        u = (u & 0x80000000u) ? ~u : (u | 0x80000000u);   // order-preserving
        w[i] = ((unsigned long long)u << 10) | (unsigned)(N - 1 - i);
    }
    // mask sum -> k_i (0/1 values: exact in any order)
    float ms = 0.f;
    for (int i = t; i < N; i += 512) ms += mask[b * N + i];
    #pragma unroll
    for (int o = 16; o; o >>= 1) ms += __shfl_xor_sync(0xffffffffu, ms, o);
    if ((t & 31) == 0) red[t >> 5] = ms;
    __syncthreads();
    if (t == 0) {
        float s = 0.f;
        #pragma unroll
        for (int wv = 0; wv < 16; wv++) s += red[wv];
        s_ki = (int)ceilf(0.25f * s);
    }
    __syncthreads();

    unsigned long long k = w[blockIdx.x * 128 + e];
    const ulonglong2* w2 = (const ulonglong2*)w;
    int base = q * 128;         // quarter start, in ulonglong2 units
    int r0 = 0, r1 = 0, r2 = 0, r3 = 0;
    #pragma unroll 8
    for (int m = 0; m < 128; m += 4) {
        ulonglong2 a  = w2[base + m];
        ulonglong2 bb = w2[base + m + 1];
        ulonglong2 c  = w2[base + m + 2];
        ulonglong2 d  = w2[base + m + 3];
        r0 += (a.x  > k) + (a.y  > k);
        r1 += (bb.x > k) + (bb.y > k);
        r2 += (c.x  > k) + (c.y  > k);
        r3 += (d.x  > k) + (d.y  > k);
    }
    rnk[t] = r0 + r1 + r2 + r3;
    __syncthreads();

    if (t < 128) {
        int rank = rnk[t] + rnk[t + 128] + rnk[t + 256] + rnk[t + 384];
        if (rank < K) {
            int n = blockIdx.x * 128 + t;
            unsigned u = (unsigned)(k >> 10);             // recover score bits
            unsigned orig = (u & 0x80000000u) ? (u & 0x7fffffffu) : ~u;
            float val = __uint_as_float(orig);
            float nm = (rank < s_ki) ? 1.f : 0.f;
            d_idxg[b * K + rank] = n;
            d_gate[b * K + rank] = tanhf(val) * nm;
            d_nm[b * K + rank]   = nm;
            out[OUT_MASK_OFF + b * K + rank] = nm;
        }
    }
}

// ---------------------------------------------------------------------------
// K5: gather, 2 rows per block (verbatim R8). grid (128, 8), 256 threads.
//   new_X[b,i,:]   = X[b, idx[i], :] * gate[i]          (coalesced)
//   new_adj[b,i,j] = adj[b, idx[i], idx[j]] * nm[i]*nm[j]
// ---------------------------------------------------------------------------
__global__ void k_gather(const float* __restrict__ X,
                         const float* __restrict__ adj,
                         float* __restrict__ out) {
    int b = blockIdx.y, i0 = blockIdx.x * 2, t = threadIdx.x;
    __shared__ int   sidx[K];
    __shared__ float snm[K];
    __shared__ __align__(16) float srow[2][N];
    sidx[t] = d_idxg[b * K + t];
    snm[t]  = d_nm[b * K + t];
    __syncthreads();

    int ri0 = sidx[i0],     ri1 = sidx[i0 + 1];
    float nmi0 = snm[i0],   nmi1 = snm[i0 + 1];
    float g0 = d_gate[b * K + i0], g1 = d_gate[b * K + i0 + 1];

    {
        const float4* r0 = (const float4*)(adj + (size_t)b * N * N + (size_t)ri0 * N);
        const float4* r1 = (const float4*)(adj + (size_t)b * N * N + (size_t)ri1 * N);
        float4 a0 = r0[t];
        float4 a1 = r1[t];
        ((float4*)srow[0])[t] = a0;
        ((float4*)srow[1])[t] = a1;
    }
    out[((size_t)b * K + i0)     * C + t] = X[((size_t)b * N + ri0) * C + t] * g0;
    out[((size_t)b * K + i0 + 1) * C + t] = X[((size_t)b * N + ri1) * C + t] * g1;
    __syncthreads();

    int   cj  = sidx[t];
    float nmj = snm[t];
    float a0 = srow[0][cj], a1 = srow[1][cj];
    out[OUT_ADJ_OFF + ((size_t)b * K + i0)     * K + t] = a0 * nmi0 * nmj;
    out[OUT_ADJ_OFF + ((size_t)b * K + i0 + 1) * K + t] = a1 * nmi1 * nmj;
}

// ---------------------------------------------------------------------------
extern "C" void kernel_launch(void* const* d_in, const int* in_sizes, int n_in,
                              void* d_out, int out_size) {
    const float* X    = (const float*)d_in[0];
    const float* adj  = (const float*)d_in[1];
    const float* mask = (const float*)d_in[2];
    const float* Wqkv = (const float*)d_in[3];
    float* out = (float*)d_out;

    k_partial<<<dim3(NCHUNK, B), 256>>>(X);
    k_uvec<<<B, 256>>>(Wqkv);
    k_scores<<<dim3(N / 8, B), 256>>>(X, mask);
    k_rank<<<dim3(N / 128, B), 512>>>(mask, out);
    k_gather<<<dim3(K / 2, B), 256>>>(X, adj, out);
}

// round 12
// speedup vs baseline: 1.4784x; 1.4784x over previous
#include <cuda_runtime.h>
#include <math.h>

#define B 8
#define N 1024
#define C 256
#define K 256
#define C2 512
#define SCALE 0.17677669529663687f   // (C/H)^-0.5 = 1/sqrt(32)

// Output layout: [new_X (8*256*256) | new_adj (8*256*256) | new_mask (8*256)]
#define OUT_ADJ_OFF  (B*K*C)
#define OUT_MASK_OFF (2*B*K*C)

#define NCHUNK 64      // partial-sum chunks per batch (16 rows each)

// ---- scratch ----
__device__ float d_part[B*NCHUNK*C];
__device__ float d_u[B*C];
__device__ float d_scores[B*N];
__device__ int   d_idxg[B*K];
__device__ float d_gate[B*K];
__device__ float d_nm[B*K];

// ---------------------------------------------------------------------------
// K1: partial column sums of X (verbatim R2 — proven rounding).
// ---------------------------------------------------------------------------
__global__ void k_partial(const float* __restrict__ X) {
    int b = blockIdx.y, ch = blockIdx.x, c = threadIdx.x;
    const float* xp = X + ((size_t)b * N + (size_t)ch * 16) * C + c;
    float s = 0.f;
    #pragma unroll
    for (int r = 0; r < 16; r++) s += xp[(size_t)r * C];
    d_part[(b * NCHUNK + ch) * C + c] = s;
}

// ---------------------------------------------------------------------------
// K2: Xsum finish + two matvecs (verbatim R2 — proven rounding).
// ---------------------------------------------------------------------------
__global__ void k_uvec(const float* __restrict__ Wqkv) {
    int b = blockIdx.x, t = threadIdx.x;
    __shared__ float xs[C];
    __shared__ float ks[C];
    float s = 0.f;
    #pragma unroll
    for (int ch = 0; ch < NCHUNK; ch++) s += d_part[(b * NCHUNK + ch) * C + t];
    xs[t] = s;
    __syncthreads();
    float ka = 0.f;
    for (int c = 0; c < C; c++) ka += xs[c] * Wqkv[(size_t)c * C2 + C + t];
    ks[t] = ka;
    __syncthreads();
    const float* wrow = Wqkv + (size_t)t * C2;
    float ua = 0.f;
    for (int j = 0; j < C; j++) ua += wrow[j] * ks[j];
    d_u[b * C + t] = ua;
}

// ---------------------------------------------------------------------------
// K3: scores (verbatim R2 — proven rounding).
// ---------------------------------------------------------------------------
__global__ void k_scores(const float* __restrict__ X,
                         const float* __restrict__ mask) {
    int b = blockIdx.y, t = threadIdx.x;
    __shared__ float us[C];
    us[t] = d_u[b * C + t];
    __syncthreads();
    int warp = t >> 5, lane = t & 31;
    int n = blockIdx.x * 8 + warp;
    const float4* xr = (const float4*)(X + ((size_t)b * N + n) * C);
    const float4* ur = (const float4*)us;
    float acc = 0.f;
    #pragma unroll
    for (int it = 0; it < 2; it++) {
        float4 xv = xr[lane + it * 32];
        float4 uv = ur[lane + it * 32];
        acc += xv.x * uv.x + xv.y * uv.y + xv.z * uv.z + xv.w * uv.w;
    }
    #pragma unroll
    for (int o = 16; o; o >>= 1) acc += __shfl_xor_sync(0xffffffffu, acc, o);
    if (lane == 0) {
        float m = mask[b * N + n];
        d_scores[b * N + n] = (m > 0.f) ? SCALE * acc : -1e9f;
    }
}

// ---------------------------------------------------------------------------
// K4: top-k (verbatim R2 — best measured top-k, proven).
// Hybrid bitonic: j>=32 via shared, j<=16 via warp shuffle.
// Key = (~orderedFloat(score) << 32) | idx ; ascending == desc score,
// ascending index tie-break (matches jax.lax.top_k).
// ---------------------------------------------------------------------------
__global__ void __launch_bounds__(1024, 1)
k_topk(const float* __restrict__ mask, float* __restrict__ out) {
    int b = blockIdx.x, t = threadIdx.x;
    __shared__ unsigned long long sk[N];
    __shared__ float red[32];
    __shared__ int s_ki;

    float f = d_scores[b * N + t];
    unsigned u = __float_as_uint(f);
    u = (u & 0x80000000u) ? ~u : (u | 0x80000000u);
    unsigned long long v = ((unsigned long long)(~u) << 32) | (unsigned)t;

    float ms = mask[b * N + t];
    #pragma unroll
    for (int o = 16; o; o >>= 1) ms += __shfl_xor_sync(0xffffffffu, ms, o);
    if ((t & 31) == 0) red[t >> 5] = ms;
    __syncthreads();
    if (t == 0) {
        float s = 0.f;
        #pragma unroll
        for (int w = 0; w < 32; w++) s += red[w];
        s_ki = (int)ceilf(0.25f * s);
    }

    #pragma unroll
    for (unsigned k = 2; k <= 1024; k <<= 1) {
        bool dir_up = ((t & k) == 0);
        for (unsigned j = k >> 1; j >= 32; j >>= 1) {
            sk[t] = v;
            __syncthreads();
            unsigned long long w = sk[t ^ j];
            bool lower = ((t & j) == 0);
            bool takeMin = (lower == dir_up);
            v = takeMin ? (v < w ? v : w) : (v > w ? v : w);
            __syncthreads();
        }
        unsigned jstart = (k >> 1) < 16u ? (k >> 1) : 16u;
        for (unsigned j = jstart; j >= 1; j >>= 1) {
            unsigned long long w = __shfl_xor_sync(0xffffffffu, v, j);
            bool lower = ((t & j) == 0);
            bool takeMin = (lower == dir_up);
            v = takeMin ? (v < w ? v : w) : (v > w ? v : w);
        }
    }
    sk[t] = v;
    __syncthreads();

    if (t < K) {
        unsigned long long key = sk[t];
        int n = (int)(unsigned)key;
        unsigned uh = ~(unsigned)(key >> 32);
        unsigned orig = (uh & 0x80000000u) ? (uh & 0x7fffffffu) : ~uh;
        float val = __uint_as_float(orig);
        float nm = (t < s_ki) ? 1.f : 0.f;
        d_idxg[b * K + t] = n;
        d_gate[b * K + t] = tanhf(val) * nm;
        d_nm[b * K + t]   = nm;
        out[OUT_MASK_OFF + b * K + t] = nm;
    }
}

// ---------------------------------------------------------------------------
// K5: gather, 4 rows per block, 512 threads. grid (64, 8).
//   new_X[b,i,:]   = X[b, idx[i], :] * gate[i]
//   new_adj[b,i,j] = adj[b, idx[i], idx[j]] * nm[i]*nm[j]
// 4 adj rows (16KB) staged coalesced with many loads in flight; idx/nm load
// and barrier amortized over 4 output rows; 16 warps hide gmem latency.
// ---------------------------------------------------------------------------
__global__ void k_gather(const float* __restrict__ X,
                         const float* __restrict__ adj,
                         float* __restrict__ out) {
    int b = blockIdx.y, i0 = blockIdx.x * 4, t = threadIdx.x;
    __shared__ int   sidx[K];
    __shared__ float snm[K];
    __shared__ float sg[4];
    __shared__ __align__(16) float srow[4][N];

    if (t < 256) {
        sidx[t] = d_idxg[b * K + t];
        snm[t]  = d_nm[b * K + t];
    }
    if (t >= 256 && t < 260) sg[t - 256] = d_gate[b * K + i0 + (t - 256)];
    __syncthreads();

    // stage 4 adj rows: 1024 float4 transfers over 512 threads (2 each,
    // independent => 2+2 loads in flight with the X reads below)
    const float* adjb = adj + (size_t)b * N * N;
    #pragma unroll
    for (int rr = 0; rr < 2; rr++) {
        int lin = rr * 512 + t;           // 0..1023
        int row = lin >> 8;               // 0..3
        int q   = lin & 255;              // float4 index in row
        const float4* src = (const float4*)(adjb + (size_t)sidx[i0 + row] * N);
        ((float4*)srow[row])[q] = src[q];
    }
    // new_X rows (coalesced): 1024 elements over 512 threads
    #pragma unroll
    for (int rr = 0; rr < 2; rr++) {
        int lin = rr * 512 + t;
        int row = lin >> 8;
        int col = lin & 255;
        int ri  = sidx[i0 + row];
        out[((size_t)b * K + i0 + row) * C + col] =
            X[((size_t)b * N + ri) * C + col] * sg[row];
    }
    __syncthreads();

    // adj outputs: 1024 elements over 512 threads, coalesced writes
    #pragma unroll
    for (int rr = 0; rr < 2; rr++) {
        int lin = rr * 512 + t;
        int row = lin >> 8;
        int j   = lin & 255;
        float v = srow[row][sidx[j]] * snm[i0 + row] * snm[j];
        out[OUT_ADJ_OFF + ((size_t)b * K + i0 + row) * K + j] = v;
    }
}

// ---------------------------------------------------------------------------
extern "C" void kernel_launch(void* const* d_in, const int* in_sizes, int n_in,
                              void* d_out, int out_size) {
    const float* X    = (const float*)d_in[0];
    const float* adj  = (const float*)d_in[1];
    const float* mask = (const float*)d_in[2];
    const float* Wqkv = (const float*)d_in[3];
    float* out = (float*)d_out;

    k_partial<<<dim3(NCHUNK, B), 256>>>(X);
    k_uvec<<<B, 256>>>(Wqkv);
    k_scores<<<dim3(N / 8, B), 256>>>(X, mask);
    k_topk<<<B, 1024>>>(mask, out);
    k_gather<<<dim3(K / 4, B), 512>>>(X, adj, out);
}

// round 13
// speedup vs baseline: 1.5281x; 1.0336x over previous
#include <cuda_runtime.h>
#include <math.h>

#define B 8
#define N 1024
#define C 256
#define K 256
#define C2 512
#define SCALE 0.17677669529663687f   // (C/H)^-0.5 = 1/sqrt(32)

// Output layout: [new_X (8*256*256) | new_adj (8*256*256) | new_mask (8*256)]
#define OUT_ADJ_OFF  (B*K*C)
#define OUT_MASK_OFF (2*B*K*C)

#define NCHUNK 64      // partial-sum chunks per batch (16 rows each)

// ---- scratch ----
__device__ float d_part[B*NCHUNK*C];
__device__ float d_u[B*C];
__device__ float d_scores[B*N];
__device__ int   d_idxg[B*K];
__device__ float d_gate[B*K];
__device__ float d_nm[B*K];

// ---------------------------------------------------------------------------
// K1: partial column sums of X (verbatim R2 — proven rounding).
// ---------------------------------------------------------------------------
__global__ void k_partial(const float* __restrict__ X) {
    int b = blockIdx.y, ch = blockIdx.x, c = threadIdx.x;
    const float* xp = X + ((size_t)b * N + (size_t)ch * 16) * C + c;
    float s = 0.f;
    #pragma unroll
    for (int r = 0; r < 16; r++) s += xp[(size_t)r * C];
    d_part[(b * NCHUNK + ch) * C + c] = s;
}

// ---------------------------------------------------------------------------
// K2: Xsum finish + two matvecs (verbatim R2 — proven rounding).
// ---------------------------------------------------------------------------
__global__ void k_uvec(const float* __restrict__ Wqkv) {
    int b = blockIdx.x, t = threadIdx.x;
    __shared__ float xs[C];
    __shared__ float ks[C];
    float s = 0.f;
    #pragma unroll
    for (int ch = 0; ch < NCHUNK; ch++) s += d_part[(b * NCHUNK + ch) * C + t];
    xs[t] = s;
    __syncthreads();
    float ka = 0.f;
    for (int c = 0; c < C; c++) ka += xs[c] * Wqkv[(size_t)c * C2 + C + t];
    ks[t] = ka;
    __syncthreads();
    const float* wrow = Wqkv + (size_t)t * C2;
    float ua = 0.f;
    for (int j = 0; j < C; j++) ua += wrow[j] * ks[j];
    d_u[b * C + t] = ua;
}

// ---------------------------------------------------------------------------
// K3: scores (verbatim R2 — proven rounding).
// ---------------------------------------------------------------------------
__global__ void k_scores(const float* __restrict__ X,
                         const float* __restrict__ mask) {
    int b = blockIdx.y, t = threadIdx.x;
    __shared__ float us[C];
    us[t] = d_u[b * C + t];
    __syncthreads();
    int warp = t >> 5, lane = t & 31;
    int n = blockIdx.x * 8 + warp;
    const float4* xr = (const float4*)(X + ((size_t)b * N + n) * C);
    const float4* ur = (const float4*)us;
    float acc = 0.f;
    #pragma unroll
    for (int it = 0; it < 2; it++) {
        float4 xv = xr[lane + it * 32];
        float4 uv = ur[lane + it * 32];
        acc += xv.x * uv.x + xv.y * uv.y + xv.z * uv.z + xv.w * uv.w;
    }
    #pragma unroll
    for (int o = 16; o; o >>= 1) acc += __shfl_xor_sync(0xffffffffu, acc, o);
    if (lane == 0) {
        float m = mask[b * N + n];
        d_scores[b * N + n] = (m > 0.f) ? SCALE * acc : -1e9f;
    }
}

// ---------------------------------------------------------------------------
// K4: top-k. Virtual-processor bitonic: 256 threads x 4 elements,
// element e = t + 256*m (m = 0..3). Stage (k, j):
//   up(e)    = ((e & k) == 0) ; lower(e) = ((e & j) == 0)
//   j >= 256 : partner in-thread across m-slices (register exchange)
//   32<=j<=128: partner t^j, same m (shared exchange, 12 stages, 8-warp bars)
//   j <= 16  : partner t^j, same m (warp shuffle, 4-way ILP)
// e&k for k<=128 == t&k; e&256 = (m&1)<<8; e&512 = (m&2)<<8; e&1024 = 0.
// Keys identical to the R2/R6-proven sorts (pure integer compares) =>
// bit-identical selection; ascending order == descending score with
// ascending-index tie-break (matches jax.lax.top_k).
// After the full sort, v[0] of thread t holds rank t (t = 0..255).
// ---------------------------------------------------------------------------
__global__ void __launch_bounds__(256, 1)
k_topk(const float* __restrict__ mask, float* __restrict__ out) {
    int b = blockIdx.x, t = threadIdx.x;
    __shared__ unsigned long long sx[4][256];    // 8KB
    __shared__ float red[8];
    __shared__ int s_ki;

    unsigned long long v[4];
    float msum = 0.f;
    #pragma unroll
    for (int m = 0; m < 4; m++) {
        int e = t + 256 * m;
        float f = d_scores[b * N + e];
        unsigned u = __float_as_uint(f);
        u = (u & 0x80000000u) ? ~u : (u | 0x80000000u);   // order-preserving
        v[m] = ((unsigned long long)(~u) << 32) | (unsigned)e;
        msum += mask[b * N + e];
    }
    // mask sum -> k_i (0/1 values: exact in any order)
    #pragma unroll
    for (int o = 16; o; o >>= 1) msum += __shfl_xor_sync(0xffffffffu, msum, o);
    if ((t & 31) == 0) red[t >> 5] = msum;
    __syncthreads();
    if (t == 0) {
        float s = 0.f;
        #pragma unroll
        for (int w = 0; w < 8; w++) s += red[w];
        s_ki = (int)ceilf(0.25f * s);
    }
    __syncthreads();

    #pragma unroll
    for (unsigned k = 2; k <= 1024; k <<= 1) {
        #pragma unroll
        for (unsigned j = 512; j > 0; j >>= 1) {
            if (j > (k >> 1)) continue;
            if (j >= 256) {
                // in-register exchange across m-slices: pairs (m, m | jm)
                int jm = (int)(j >> 8);                    // 1 or 2
                #pragma unroll
                for (int m = 0; m < 4; m++) {
                    if ((m & jm) == 0) {
                        int mp = m | jm;
                        // up(e_m): k==512 -> ((m&2)==0); k==1024 -> true
                        bool up = (k == 1024) ? true : ((m & 2) == 0);
                        unsigned long long a = v[m], bb = v[mp];
                        unsigned long long mn = a < bb ? a : bb;
                        unsigned long long mx = a < bb ? bb : a;
                        v[m]  = up ? mn : mx;
                        v[mp] = up ? mx : mn;
                    }
                }
            } else if (j >= 32) {
                // shared exchange: partner t^j, same m
                #pragma unroll
                for (int m = 0; m < 4; m++) sx[m][t] = v[m];
                __syncthreads();
                bool lower = ((t & j) == 0);
                #pragma unroll
                for (int m = 0; m < 4; m++) {
                    bool up;
                    if (k <= 128)       up = ((t & k) == 0);
                    else if (k == 256)  up = ((m & 1) == 0);
                    else if (k == 512)  up = ((m & 2) == 0);
                    else                up = true;
                    unsigned long long w = sx[m][t ^ j];
                    bool takeMin = (lower == up);
                    v[m] = takeMin ? (v[m] < w ? v[m] : w)
                                   : (v[m] > w ? v[m] : w);
                }
                __syncthreads();
            } else {
                // warp shuffle exchange: distance j <= 16
                bool lower = ((t & j) == 0);
                #pragma unroll
                for (int m = 0; m < 4; m++) {
                    bool up;
                    if (k <= 128)       up = ((t & k) == 0);
                    else if (k == 256)  up = ((m & 1) == 0);
                    else if (k == 512)  up = ((m & 2) == 0);
                    else                up = true;
                    unsigned long long w = __shfl_xor_sync(0xffffffffu, v[m], j);
                    bool takeMin = (lower == up);
                    v[m] = takeMin ? (v[m] < w ? v[m] : w)
                                   : (v[m] > w ? v[m] : w);
                }
            }
        }
    }

    // rank t == v[0] of thread t (ascending full sort)
    {
        unsigned long long key = v[0];
        int n = (int)(unsigned)key;
        unsigned uh = ~(unsigned)(key >> 32);              // recover score bits
        unsigned orig = (uh & 0x80000000u) ? (uh & 0x7fffffffu) : ~uh;
        float val = __uint_as_float(orig);
        float nm = (t < s_ki) ? 1.f : 0.f;
        d_idxg[b * K + t] = n;
        d_gate[b * K + t] = tanhf(val) * nm;
        d_nm[b * K + t]   = nm;
        out[OUT_MASK_OFF + b * K + t] = nm;
    }
}

// ---------------------------------------------------------------------------
// K5: gather, 4 rows per block, 512 threads (verbatim R12). grid (64, 8).
//   new_X[b,i,:]   = X[b, idx[i], :] * gate[i]
//   new_adj[b,i,j] = adj[b, idx[i], idx[j]] * nm[i]*nm[j]
// ---------------------------------------------------------------------------
__global__ void k_gather(const float* __restrict__ X,
                         const float* __restrict__ adj,
                         float* __restrict__ out) {
    int b = blockIdx.y, i0 = blockIdx.x * 4, t = threadIdx.x;
    __shared__ int   sidx[K];
    __shared__ float snm[K];
    __shared__ float sg[4];
    __shared__ __align__(16) float srow[4][N];

    if (t < 256) {
        sidx[t] = d_idxg[b * K + t];
        snm[t]  = d_nm[b * K + t];
    }
    if (t >= 256 && t < 260) sg[t - 256] = d_gate[b * K + i0 + (t - 256)];
    __syncthreads();

    const float* adjb = adj + (size_t)b * N * N;
    #pragma unroll
    for (int rr = 0; rr < 2; rr++) {
        int lin = rr * 512 + t;
        int row = lin >> 8;
        int q   = lin & 255;
        const float4* src = (const float4*)(adjb + (size_t)sidx[i0 + row] * N);
        ((float4*)srow[row])[q] = src[q];
    }
    #pragma unroll
    for (int rr = 0; rr < 2; rr++) {
        int lin = rr * 512 + t;
        int row = lin >> 8;
        int col = lin & 255;
        int ri  = sidx[i0 + row];
        out[((size_t)b * K + i0 + row) * C + col] =
            X[((size_t)b * N + ri) * C + col] * sg[row];
    }
    __syncthreads();

    #pragma unroll
    for (int rr = 0; rr < 2; rr++) {
        int lin = rr * 512 + t;
        int row = lin >> 8;
        int j   = lin & 255;
        float vv = srow[row][sidx[j]] * snm[i0 + row] * snm[j];
        out[OUT_ADJ_OFF + ((size_t)b * K + i0 + row) * K + j] = vv;
    }
}

// ---------------------------------------------------------------------------
extern "C" void kernel_launch(void* const* d_in, const int* in_sizes, int n_in,
                              void* d_out, int out_size) {
    const float* X    = (const float*)d_in[0];
    const float* adj  = (const float*)d_in[1];
    const float* mask = (const float*)d_in[2];
    const float* Wqkv = (const float*)d_in[3];
    float* out = (float*)d_out;

    k_partial<<<dim3(NCHUNK, B), 256>>>(X);
    k_uvec<<<B, 256>>>(Wqkv);
    k_scores<<<dim3(N / 8, B), 256>>>(X, mask);
    k_topk<<<B, 256>>>(mask, out);
    k_gather<<<dim3(K / 4, B), 512>>>(X, adj, out);
}